// round 10
// baseline (speedup 1.0000x reference)
#include <cuda_runtime.h>

// ---------------- complex float helpers ----------------
struct cf { float x, y; };
__device__ __forceinline__ cf cmul(cf a, cf b) { return {a.x*b.x - a.y*b.y, a.x*b.y + a.y*b.x}; }

__device__ __forceinline__ cf shfl_cf(cf v, int src) {
    cf r;
    r.x = __shfl_sync(0xffffffffu, v.x, src);
    r.y = __shfl_sync(0xffffffffu, v.y, src);
    return r;
}

// Published coefficients (3 x float4 for vector loads; 9 used) + ready flag.
// Monotone across graph replays: block 0 rewrites bitwise-identical values
// every launch, so any race with late readers is benign.
__device__ float4 g_coef4[3];
__device__ int    g_flag;

// Rot(phi,theta,omega) matrix entry (i,j) from precomputed trig.
__device__ __forceinline__ cf rot_entry(int i, int j,
                                        float cp, float sp, float cm, float sm,
                                        float c, float s) {
    cf r;
    if (i == 0) { if (j == 0) r = { cp*c, -sp*c }; else r = { -cm*s, -sm*s }; }
    else        { if (j == 0) r = { cm*s, -sm*s }; else r = {  cp*c,  sp*c }; }
    return r;
}

// Warp-collective coefficient derivation (lanes 0-15 own U[r][cc]; 16-31
// duplicate). Lane 0 ends with the 16 Q entries in sQ. Numerics verified
// (rel_err 4.65e-07 in R7/R8/R9).
__device__ __forceinline__ void warp_compute_Q(const float* __restrict__ qw,
                                               float* __restrict__ sQ,
                                               int lane) {
    int r  = (lane >> 2) & 3;
    int cc = lane & 3;
    // Combined CNOT(0,1);CNOT(1,0) row permutation: new[r] = old[perm[r]]
    int pr = (r == 0) ? 0 : (r == 1) ? 2 : (r == 2) ? 3 : 1;
    int ai = pr >> 1, ak = pr & 1, aj = cc >> 1, am = cc & 1;

    cf u = { (r == cc) ? 1.0f : 0.0f, 0.0f };   // U[r][cc], U = I

#pragma unroll
    for (int l = 0; l < 3; l++) {
        float c0t, s0t, cp0, sp0, cm0, sm0;
        float c1t, s1t, cp1, sp1, cm1, sm1;
        {
            float phi = qw[l*6+0], th = qw[l*6+1], om = qw[l*6+2];
            __sincosf(0.5f*th, &s0t, &c0t);
            __sincosf(0.5f*(phi+om), &sp0, &cp0);
            __sincosf(0.5f*(phi-om), &sm0, &cm0);
        }
        {
            float phi = qw[l*6+3], th = qw[l*6+4], om = qw[l*6+5];
            __sincosf(0.5f*th, &s1t, &c1t);
            __sincosf(0.5f*(phi+om), &sp1, &cp1);
            __sincosf(0.5f*(phi-om), &sm1, &cm1);
        }
        // A_p[r][cc] = A[perm[r]][cc] = R0[ai][aj] * R1[ak][am]
        cf r0 = rot_entry(ai, aj, cp0, sp0, cm0, sm0, c0t, s0t);
        cf r1 = rot_entry(ak, am, cp1, sp1, cm1, sm1, c1t, s1t);
        cf a  = cmul(r0, r1);

        // U <- A_p * U
        cf acc = {0.0f, 0.0f};
#pragma unroll
        for (int t = 0; t < 4; t++) {
            cf at = shfl_cf(a, r*4 + t);
            cf ut = shfl_cf(u, t*4 + cc);
            cf p = cmul(at, ut);
            acc.x += p.x; acc.y += p.y;
        }
        u = acc;
    }

    // M[j][k] = sum_n z_n conj(U[n][j]) U[n][k],  j=r, k=cc, z=diag(1,1,-1,-1)
    cf M = {0.0f, 0.0f};
#pragma unroll
    for (int n = 0; n < 4; n++) {
        float zn = (n < 2) ? 1.0f : -1.0f;
        cf unj = shfl_cf(u, n*4 + r);
        cf unk = shfl_cf(u, n*4 + cc);
        cf t = { unj.x*unk.x + unj.y*unk.y, unj.x*unk.y - unj.y*unk.x };
        M.x += zn * t.x; M.y += zn * t.y;
    }
    // Q[j][k] = Re( conj(d_j) d_k M[j][k] ), d = (1, -i, -i, -1)
    cf dj = (r  == 0) ? cf{1.f,0.f} : (r  == 3) ? cf{-1.f,0.f} : cf{0.f,-1.f};
    cf dk = (cc == 0) ? cf{1.f,0.f} : (cc == 3) ? cf{-1.f,0.f} : cf{0.f,-1.f};
    cf e = cmul(cf{dj.x, -dj.y}, dk);
    float Q = e.x*M.x - e.y*M.y;

    if (lane < 16) sQ[lane] = Q;
    __syncwarp();
}

// ---------------- per-element evaluation ----------------
__device__ __forceinline__ float eval_elem(float x0, float x1, const float* c) {
    float s0, c0, s1, c1;
    __sincosf(x0, &s0, &c0);
    __sincosf(x1, &s1, &c1);
    float t0 = fmaf(c[1], c0, fmaf(c[2], s0, c[0]));
    float t1 = fmaf(c[4], c0, fmaf(c[5], s0, c[3]));
    float t2 = fmaf(c[7], c0, fmaf(c[8], s0, c[6]));
    return fmaf(c1, t1, fmaf(s1, t2, t0));
}

__global__ void __launch_bounds__(256, 6)
qlayer_one(const float4* __restrict__ x, const float* __restrict__ qw,
           float4* __restrict__ out, int n4) {
    __shared__ float sQ[16];
    __shared__ float sc[12];

    int i = blockIdx.x * blockDim.x + threadIdx.x;
    bool active = (i < n4);

    // Front-batch both 128-bit loads first: their DRAM latency (~600 cyc)
    // covers the warp-0 coefficient acquisition below.
    float4 a = make_float4(0.f,0.f,0.f,0.f);
    float4 b = make_float4(0.f,0.f,0.f,0.f);
    if (active) {
        a = __ldg(&x[2*i]);
        b = __ldg(&x[2*i + 1]);
    }

    if (blockIdx.x == 0) {
        // Producer block: warp 0 derives the coefficients and publishes them.
        if (threadIdx.x < 32) {
            warp_compute_Q(qw, sQ, threadIdx.x);
            if (threadIdx.x == 0) {
                float Q00=sQ[0],  Q01=sQ[1],  Q02=sQ[2],  Q03=sQ[3];
                float Q11=sQ[5],  Q12=sQ[6],  Q13=sQ[7];
                float Q22=sQ[10], Q23=sQ[11], Q33=sQ[15];
                float c0 = (Q00+Q11+Q22+Q33)*0.25f;  // 1
                float c1 = (Q00+Q11-Q22-Q33)*0.25f;  // C0
                float c2 = (Q02+Q13)*0.5f;           // S0
                float c3 = (Q00-Q11+Q22-Q33)*0.25f;  // C1
                float c4 = (Q00-Q11-Q22+Q33)*0.25f;  // C0*C1
                float c5 = (Q02-Q13)*0.5f;           // S0*C1
                float c6 = (Q01+Q23)*0.5f;           // S1
                float c7 = (Q01-Q23)*0.5f;           // C0*S1
                float c8 = (Q03+Q12)*0.5f;           // S0*S1
                sc[0]=c0; sc[1]=c1; sc[2]=c2; sc[3]=c3; sc[4]=c4;
                sc[5]=c5; sc[6]=c6; sc[7]=c7; sc[8]=c8;
                g_coef4[0] = make_float4(c0, c1, c2, c3);
                g_coef4[1] = make_float4(c4, c5, c6, c7);
                g_coef4[2] = make_float4(c8, 0.f, 0.f, 0.f);
                __threadfence();          // coefs visible before flag
                g_flag = 1;
            }
        }
    } else {
        // Consumer blocks: ONLY lane 0 of warp 0 polls the flag and fetches
        // the coefficients — all other threads go straight to the barrier
        // with their LDGs in flight (R8's per-thread fence/poll was the bug).
        if (threadIdx.x == 0) {
            while (__ldcg(&g_flag) == 0) __nanosleep(64);
            __threadfence();              // acquire: order coef loads after flag
            float4 v0 = __ldcg(&g_coef4[0]);
            float4 v1 = __ldcg(&g_coef4[1]);
            float4 v2 = __ldcg(&g_coef4[2]);
            sc[0]=v0.x; sc[1]=v0.y; sc[2]=v0.z; sc[3]=v0.w;
            sc[4]=v1.x; sc[5]=v1.y; sc[6]=v1.z; sc[7]=v1.w;
            sc[8]=v2.x;
        }
    }
    __syncthreads();

    float c[9];
#pragma unroll
    for (int j = 0; j < 9; j++) c[j] = sc[j];

    if (active) {
        float4 r;
        r.x = eval_elem(a.x, a.y, c);
        r.y = eval_elem(a.z, a.w, c);
        r.z = eval_elem(b.x, b.y, c);
        r.w = eval_elem(b.z, b.w, c);
        out[i] = r;
    }
}

// Tail kernel (only launched if out_size % 4 != 0; never for B=4M).
// Runs after qlayer_one in-stream, so g_coef4 is already published.
__global__ void qlayer_tail(const float2* __restrict__ x, float* __restrict__ out,
                            int start, int n) {
    int i = start + (int)threadIdx.x;
    if (i < n) {
        float4 v0 = __ldcg(&g_coef4[0]);
        float4 v1 = __ldcg(&g_coef4[1]);
        float4 v2 = __ldcg(&g_coef4[2]);
        float c[9] = {v0.x,v0.y,v0.z,v0.w, v1.x,v1.y,v1.z,v1.w, v2.x};
        float2 v = x[i];
        out[i] = eval_elem(v.x, v.y, c);
    }
}

extern "C" void kernel_launch(void* const* d_in, const int* in_sizes, int n_in,
                              void* d_out, int out_size) {
    const float* x  = (const float*)d_in[0];   // [B, 2]
    const float* qw = (const float*)d_in[1];   // [3, 2, 3]

    int n4 = out_size / 4;                     // 4 elements per thread
    int threads = 256;
    int blocks = (n4 + threads - 1) / threads;
    if (blocks > 0)
        qlayer_one<<<blocks, threads>>>((const float4*)x, qw, (float4*)d_out, n4);

    int done = n4 * 4;
    if (done < out_size) {
        qlayer_tail<<<1, 32>>>((const float2*)x, (float*)d_out, done, out_size);
    }
}

// round 11
// speedup vs baseline: 1.0175x; 1.0175x over previous
#include <cuda_runtime.h>

// ---------------- complex float helpers ----------------
struct cf { float x, y; };
__device__ __forceinline__ cf cmul(cf a, cf b) { return {a.x*b.x - a.y*b.y, a.x*b.y + a.y*b.x}; }

__device__ __forceinline__ cf shfl_cf(cf v, int src) {
    cf r;
    r.x = __shfl_sync(0xffffffffu, v.x, src);
    r.y = __shfl_sync(0xffffffffu, v.y, src);
    return r;
}

// 9 bilinear coefficients: [const, C0, S0, C1, C0C1, S0C1, S1, C0S1, S0S1]
__device__ float g_coef[9];

// Rot(phi,theta,omega) matrix entry (i,j) from precomputed trig.
__device__ __forceinline__ cf rot_entry(int i, int j,
                                        float cp, float sp, float cm, float sm,
                                        float c, float s) {
    cf r;
    if (i == 0) { if (j == 0) r = { cp*c, -sp*c }; else r = { -cm*s, -sm*s }; }
    else        { if (j == 0) r = { cm*s, -sm*s }; else r = {  cp*c,  sp*c }; }
    return r;
}

// Warp-parallel setup (numerics verified across R7-R10: rel_err 4.65e-07).
// Lanes 0-15 own entry (r,cc) of the running 4x4 complex unitary.
__global__ void setup_kernel(const float* __restrict__ qw) {
    __shared__ float sQ[16];
    int lane = threadIdx.x;

    int r  = (lane >> 2) & 3;
    int cc = lane & 3;
    // Combined CNOT(0,1);CNOT(1,0) row permutation: new[r] = old[perm[r]]
    int pr = (r == 0) ? 0 : (r == 1) ? 2 : (r == 2) ? 3 : 1;
    int ai = pr >> 1, ak = pr & 1, aj = cc >> 1, am = cc & 1;

    cf u = { (r == cc) ? 1.0f : 0.0f, 0.0f };   // U[r][cc], U = I

#pragma unroll
    for (int l = 0; l < 3; l++) {
        float c0t, s0t, cp0, sp0, cm0, sm0;
        float c1t, s1t, cp1, sp1, cm1, sm1;
        {
            float phi = qw[l*6+0], th = qw[l*6+1], om = qw[l*6+2];
            __sincosf(0.5f*th, &s0t, &c0t);
            __sincosf(0.5f*(phi+om), &sp0, &cp0);
            __sincosf(0.5f*(phi-om), &sm0, &cm0);
        }
        {
            float phi = qw[l*6+3], th = qw[l*6+4], om = qw[l*6+5];
            __sincosf(0.5f*th, &s1t, &c1t);
            __sincosf(0.5f*(phi+om), &sp1, &cp1);
            __sincosf(0.5f*(phi-om), &sm1, &cm1);
        }
        // A_p[r][cc] = A[perm[r]][cc] = R0[ai][aj] * R1[ak][am]
        cf r0 = rot_entry(ai, aj, cp0, sp0, cm0, sm0, c0t, s0t);
        cf r1 = rot_entry(ak, am, cp1, sp1, cm1, sm1, c1t, s1t);
        cf a  = cmul(r0, r1);

        // U <- A_p * U
        cf acc = {0.0f, 0.0f};
#pragma unroll
        for (int t = 0; t < 4; t++) {
            cf at = shfl_cf(a, r*4 + t);
            cf ut = shfl_cf(u, t*4 + cc);
            cf p = cmul(at, ut);
            acc.x += p.x; acc.y += p.y;
        }
        u = acc;
    }

    // M[j][k] = sum_n z_n conj(U[n][j]) U[n][k],  z = diag(1,1,-1,-1)
    cf M = {0.0f, 0.0f};
#pragma unroll
    for (int n = 0; n < 4; n++) {
        float zn = (n < 2) ? 1.0f : -1.0f;
        cf unj = shfl_cf(u, n*4 + r);
        cf unk = shfl_cf(u, n*4 + cc);
        cf t = { unj.x*unk.x + unj.y*unk.y, unj.x*unk.y - unj.y*unk.x };
        M.x += zn * t.x; M.y += zn * t.y;
    }
    // Q[j][k] = Re( conj(d_j) d_k M[j][k] ), d = (1, -i, -i, -1)
    cf dj = (r  == 0) ? cf{1.f,0.f} : (r  == 3) ? cf{-1.f,0.f} : cf{0.f,-1.f};
    cf dk = (cc == 0) ? cf{1.f,0.f} : (cc == 3) ? cf{-1.f,0.f} : cf{0.f,-1.f};
    cf e = cmul(cf{dj.x, -dj.y}, dk);
    float Q = e.x*M.x - e.y*M.y;

    if (lane < 16) sQ[lane] = Q;
    __syncwarp();
    if (lane == 0) {
        float Q00=sQ[0],  Q01=sQ[1],  Q02=sQ[2],  Q03=sQ[3];
        float Q11=sQ[5],  Q12=sQ[6],  Q13=sQ[7];
        float Q22=sQ[10], Q23=sQ[11], Q33=sQ[15];
        g_coef[0] = (Q00+Q11+Q22+Q33)*0.25f;  // 1
        g_coef[1] = (Q00+Q11-Q22-Q33)*0.25f;  // C0
        g_coef[2] = (Q02+Q13)*0.5f;           // S0
        g_coef[3] = (Q00-Q11+Q22-Q33)*0.25f;  // C1
        g_coef[4] = (Q00-Q11-Q22+Q33)*0.25f;  // C0*C1
        g_coef[5] = (Q02-Q13)*0.5f;           // S0*C1
        g_coef[6] = (Q01+Q23)*0.5f;           // S1
        g_coef[7] = (Q01-Q23)*0.5f;           // C0*S1
        g_coef[8] = (Q03+Q12)*0.5f;           // S0*S1
    }
}

// ---------------- persistent main kernel: grid-stride + prefetch ----------------
__device__ __forceinline__ float eval_elem(float x0, float x1, const float* c) {
    float s0, c0, s1, c1;
    __sincosf(x0, &s0, &c0);
    __sincosf(x1, &s1, &c1);
    float t0 = fmaf(c[1], c0, fmaf(c[2], s0, c[0]));
    float t1 = fmaf(c[4], c0, fmaf(c[5], s0, c[3]));
    float t2 = fmaf(c[7], c0, fmaf(c[8], s0, c[6]));
    return fmaf(c1, t1, fmaf(s1, t2, t0));
}

__global__ void __launch_bounds__(256)
qlayer_kernel(const float4* __restrict__ x, float4* __restrict__ out, int n4) {
    const int stride = gridDim.x * blockDim.x;
    int i = blockIdx.x * blockDim.x + threadIdx.x;

    float c[9];
#pragma unroll
    for (int j = 0; j < 9; j++) c[j] = g_coef[j];

    if (i >= n4) return;

    // Software-pipelined grid-stride loop: next iteration's loads are issued
    // before the current iteration's math, keeping >=2 LDG.128 in flight
    // per thread at all times. Persistent grid => no wave transitions.
    float4 a = __ldg(&x[2*i]);
    float4 b = __ldg(&x[2*i + 1]);

    while (true) {
        int inext = i + stride;
        float4 an, bn;
        bool more = (inext < n4);
        if (more) {
            an = __ldg(&x[2*inext]);
            bn = __ldg(&x[2*inext + 1]);
        }

        float4 r;
        r.x = eval_elem(a.x, a.y, c);
        r.y = eval_elem(a.z, a.w, c);
        r.z = eval_elem(b.x, b.y, c);
        r.w = eval_elem(b.z, b.w, c);
        out[i] = r;

        if (!more) break;
        a = an; b = bn; i = inext;
    }
}

// Tail kernel for out_size not divisible by 4 (not hit for B=4M, defensive).
__global__ void qlayer_tail(const float2* __restrict__ x, float* __restrict__ out,
                            int start, int n) {
    int i = start + blockIdx.x * blockDim.x + threadIdx.x;
    if (i >= n) return;
    float c[9];
#pragma unroll
    for (int j = 0; j < 9; j++) c[j] = g_coef[j];
    float2 v = x[i];
    out[i] = eval_elem(v.x, v.y, c);
}

extern "C" void kernel_launch(void* const* d_in, const int* in_sizes, int n_in,
                              void* d_out, int out_size) {
    const float* x  = (const float*)d_in[0];   // [B, 2]
    const float* qw = (const float*)d_in[1];   // [3, 2, 3]

    setup_kernel<<<1, 32>>>(qw);

    int n4 = out_size / 4;                     // 4 elements per thread-iteration
    int threads = 256;
    // Persistent grid: 6 blocks x 148 SMs; never exceed the work size.
    int want = 148 * 6;
    int need = (n4 + threads - 1) / threads;
    int blocks = (need < want) ? need : want;
    if (blocks > 0)
        qlayer_kernel<<<blocks, threads>>>((const float4*)x, (float4*)d_out, n4);

    int done = n4 * 4;
    if (done < out_size) {
        int rem = out_size - done;
        qlayer_tail<<<(rem + 127) / 128, 128>>>((const float2*)x, (float*)d_out,
                                                done, out_size);
    }
}

// round 12
// speedup vs baseline: 1.2149x; 1.1940x over previous
#include <cuda_runtime.h>

// ---------------- complex float helpers ----------------
struct cf { float x, y; };
__device__ __forceinline__ cf cmul(cf a, cf b) { return {a.x*b.x - a.y*b.y, a.x*b.y + a.y*b.x}; }

__device__ __forceinline__ cf shfl_cf(cf v, int src) {
    cf r;
    r.x = __shfl_sync(0xffffffffu, v.x, src);
    r.y = __shfl_sync(0xffffffffu, v.y, src);
    return r;
}

// Rot(phi,theta,omega) matrix entry (i,j) from precomputed trig.
__device__ __forceinline__ cf rot_entry(int i, int j,
                                        float cp, float sp, float cm, float sm,
                                        float c, float s) {
    cf r;
    if (i == 0) { if (j == 0) r = { cp*c, -sp*c }; else r = { -cm*s, -sm*s }; }
    else        { if (j == 0) r = { cm*s, -sm*s }; else r = {  cp*c,  sp*c }; }
    return r;
}

// Warp-collective coefficient derivation (lanes 0-15 own U[r][cc]; lanes 16-31
// duplicate). Lane 0 writes the 9 bilinear coefficients to sc.
// Numerics verified bit-stable across R7-R11 (rel_err 4.65e-07).
// Cost: ~330 warp-instructions, ~1.2k cycles latency. Called once per block.
__device__ __forceinline__ void warp_coefs_to_smem(const float* __restrict__ qw,
                                                   float* __restrict__ sQ,
                                                   float* __restrict__ sc,
                                                   int lane) {
    int r  = (lane >> 2) & 3;
    int cc = lane & 3;
    // Combined CNOT(0,1);CNOT(1,0) row permutation: new[r] = old[perm[r]]
    int pr = (r == 0) ? 0 : (r == 1) ? 2 : (r == 2) ? 3 : 1;
    int ai = pr >> 1, ak = pr & 1, aj = cc >> 1, am = cc & 1;

    cf u = { (r == cc) ? 1.0f : 0.0f, 0.0f };   // U[r][cc], U = I

#pragma unroll
    for (int l = 0; l < 3; l++) {
        float c0t, s0t, cp0, sp0, cm0, sm0;
        float c1t, s1t, cp1, sp1, cm1, sm1;
        {
            float phi = qw[l*6+0], th = qw[l*6+1], om = qw[l*6+2];
            __sincosf(0.5f*th, &s0t, &c0t);
            __sincosf(0.5f*(phi+om), &sp0, &cp0);
            __sincosf(0.5f*(phi-om), &sm0, &cm0);
        }
        {
            float phi = qw[l*6+3], th = qw[l*6+4], om = qw[l*6+5];
            __sincosf(0.5f*th, &s1t, &c1t);
            __sincosf(0.5f*(phi+om), &sp1, &cp1);
            __sincosf(0.5f*(phi-om), &sm1, &cm1);
        }
        // A_p[r][cc] = A[perm[r]][cc] = R0[ai][aj] * R1[ak][am]
        cf r0 = rot_entry(ai, aj, cp0, sp0, cm0, sm0, c0t, s0t);
        cf r1 = rot_entry(ak, am, cp1, sp1, cm1, sm1, c1t, s1t);
        cf a  = cmul(r0, r1);

        // U <- A_p * U
        cf acc = {0.0f, 0.0f};
#pragma unroll
        for (int t = 0; t < 4; t++) {
            cf at = shfl_cf(a, r*4 + t);
            cf ut = shfl_cf(u, t*4 + cc);
            cf p = cmul(at, ut);
            acc.x += p.x; acc.y += p.y;
        }
        u = acc;
    }

    // M[j][k] = sum_n z_n conj(U[n][j]) U[n][k],  z = diag(1,1,-1,-1)
    cf M = {0.0f, 0.0f};
#pragma unroll
    for (int n = 0; n < 4; n++) {
        float zn = (n < 2) ? 1.0f : -1.0f;
        cf unj = shfl_cf(u, n*4 + r);
        cf unk = shfl_cf(u, n*4 + cc);
        cf t = { unj.x*unk.x + unj.y*unk.y, unj.x*unk.y - unj.y*unk.x };
        M.x += zn * t.x; M.y += zn * t.y;
    }
    // Q[j][k] = Re( conj(d_j) d_k M[j][k] ), d = (1, -i, -i, -1)
    cf dj = (r  == 0) ? cf{1.f,0.f} : (r  == 3) ? cf{-1.f,0.f} : cf{0.f,-1.f};
    cf dk = (cc == 0) ? cf{1.f,0.f} : (cc == 3) ? cf{-1.f,0.f} : cf{0.f,-1.f};
    cf e = cmul(cf{dj.x, -dj.y}, dk);
    float Q = e.x*M.x - e.y*M.y;

    if (lane < 16) sQ[lane] = Q;
    __syncwarp();
    if (lane == 0) {
        float Q00=sQ[0],  Q01=sQ[1],  Q02=sQ[2],  Q03=sQ[3];
        float Q11=sQ[5],  Q12=sQ[6],  Q13=sQ[7];
        float Q22=sQ[10], Q23=sQ[11], Q33=sQ[15];
        sc[0] = (Q00+Q11+Q22+Q33)*0.25f;  // 1
        sc[1] = (Q00+Q11-Q22-Q33)*0.25f;  // C0
        sc[2] = (Q02+Q13)*0.5f;           // S0
        sc[3] = (Q00-Q11+Q22-Q33)*0.25f;  // C1
        sc[4] = (Q00-Q11-Q22+Q33)*0.25f;  // C0*C1
        sc[5] = (Q02-Q13)*0.5f;           // S0*C1
        sc[6] = (Q01+Q23)*0.5f;           // S1
        sc[7] = (Q01-Q23)*0.5f;           // C0*S1
        sc[8] = (Q03+Q12)*0.5f;           // S0*S1
    }
}

// ---------------- per-element evaluation ----------------
__device__ __forceinline__ float eval_elem(float x0, float x1, const float* c) {
    float s0, c0, s1, c1;
    __sincosf(x0, &s0, &c0);
    __sincosf(x1, &s1, &c1);
    float t0 = fmaf(c[1], c0, fmaf(c[2], s0, c[0]));
    float t1 = fmaf(c[4], c0, fmaf(c[5], s0, c[3]));
    float t2 = fmaf(c[7], c0, fmaf(c[8], s0, c[6]));
    return fmaf(c1, t1, fmaf(s1, t2, t0));
}

// Single persistent kernel: exactly one wave (888 blocks), so the per-block
// coefficient derivation (warp 0, ~1.2k cycles) is paid ONCE per block,
// overlapped with the block's front-batched first-iteration loads.
// No second graph node, no gridsync, no global flag, no per-wave barrier.
__global__ void __launch_bounds__(256)
qlayer_persist(const float4* __restrict__ x, const float* __restrict__ qw,
               float4* __restrict__ out, int n4) {
    __shared__ float sQ[16];
    __shared__ float sc[9];

    const int stride = gridDim.x * blockDim.x;
    int i = blockIdx.x * blockDim.x + threadIdx.x;

    // Front-batch the first iteration's loads before the coef chain/barrier
    // so their DRAM latency covers the warp-0 work.
    bool active = (i < n4);
    float4 a, b;
    if (active) {
        a = __ldg(&x[2*i]);
        b = __ldg(&x[2*i + 1]);
    }

    if (threadIdx.x < 32)
        warp_coefs_to_smem(qw, sQ, sc, threadIdx.x);
    __syncthreads();   // once per block lifetime (persistent grid = 1 wave)

    float c[9];
#pragma unroll
    for (int j = 0; j < 9; j++) c[j] = sc[j];

    if (!active) return;

    // Software-pipelined grid-stride loop: next iteration's loads issued
    // before the current iteration's math (>=2 LDG.128 in flight per thread).
    while (true) {
        int inext = i + stride;
        float4 an, bn;
        bool more = (inext < n4);
        if (more) {
            an = __ldg(&x[2*inext]);
            bn = __ldg(&x[2*inext + 1]);
        }

        float4 r;
        r.x = eval_elem(a.x, a.y, c);
        r.y = eval_elem(a.z, a.w, c);
        r.z = eval_elem(b.x, b.y, c);
        r.w = eval_elem(b.z, b.w, c);
        out[i] = r;

        if (!more) break;
        a = an; b = bn; i = inext;
    }
}

// Tail kernel (only if out_size % 4 != 0; never for B=4M). Self-contained:
// one warp derives the coefficients itself, then handles <=3 elements.
__global__ void qlayer_tail(const float2* __restrict__ x, const float* __restrict__ qw,
                            float* __restrict__ out, int start, int n) {
    __shared__ float sQ[16];
    __shared__ float sc[9];
    warp_coefs_to_smem(qw, sQ, sc, threadIdx.x);
    __syncwarp();
    int i = start + (int)threadIdx.x;
    if (i < n) {
        float2 v = x[i];
        out[i] = eval_elem(v.x, v.y, sc);
    }
}

extern "C" void kernel_launch(void* const* d_in, const int* in_sizes, int n_in,
                              void* d_out, int out_size) {
    const float* x  = (const float*)d_in[0];   // [B, 2]
    const float* qw = (const float*)d_in[1];   // [3, 2, 3]

    int n4 = out_size / 4;                     // 4 elements per thread-iteration
    int threads = 256;
    int want = 148 * 6;                        // one full persistent wave
    int need = (n4 + threads - 1) / threads;
    int blocks = (need < want) ? need : want;
    if (blocks > 0)
        qlayer_persist<<<blocks, threads>>>((const float4*)x, qw,
                                            (float4*)d_out, n4);

    int done = n4 * 4;
    if (done < out_size) {
        qlayer_tail<<<1, 32>>>((const float2*)x, qw, (float*)d_out,
                               done, out_size);
    }
}